// round 3
// baseline (speedup 1.0000x reference)
#include <cuda_runtime.h>
#include <cstdint>
#include <mma.h>
#include <math.h>

using namespace nvcuda;

#define NE 8
#define NT 2048
#define NH 2048
#define NI 4096
#define TWO_I 8192
#define NSLOT (2*NT)

// ---------------- scratch (device globals; no allocation APIs) ----------------
__device__ int   g_cnt[NE];
__device__ int   g_rows[NE * NT];             // row_id = 2*t + k assigned to expert e
__device__ float g_gw[NSLOT];                 // gating weight per row_id
__device__ float g_h [(size_t)NSLOT * TWO_I]; // GEMM1 output (gate|up), 128MB
__device__ float g_i [(size_t)NSLOT * NI];    // silu(gate)*up, 64MB

// ---------------- cp.async helpers ----------------
__device__ __forceinline__ void cpa16(float* dst, const float* src, bool pred) {
    unsigned int d = (unsigned int)__cvta_generic_to_shared(dst);
    int sz = pred ? 16 : 0;
    asm volatile("cp.async.cg.shared.global [%0], [%1], 16, %2;\n"
                 :: "r"(d), "l"(src), "r"(sz));
}
__device__ __forceinline__ void cp_commit() {
    asm volatile("cp.async.commit_group;\n");
}
template<int N>
__device__ __forceinline__ void cp_wait() {
    asm volatile("cp.async.wait_group %0;\n" :: "n"(N));
}

// ---------------- misc kernels ----------------
__global__ void k_zero_cnt() {
    if (threadIdx.x < NE) g_cnt[threadIdx.x] = 0;
}

// ---------------- router + sparsemixer ----------------
__global__ void k_router(const float* __restrict__ x, const float* __restrict__ gw) {
    int t = blockIdx.x;
    int warp = threadIdx.x >> 5, lane = threadIdx.x & 31;
    __shared__ float s[NE];
    const float* xr = x + (size_t)t * NH;
    const float* we = gw + (size_t)warp * NH;
    float acc = 0.f;
    for (int k = lane; k < NH; k += 32) acc += xr[k] * we[k];
    #pragma unroll
    for (int o = 16; o; o >>= 1) acc += __shfl_xor_sync(0xffffffffu, acc, o);
    if (lane == 0) s[warp] = acc;
    __syncthreads();
    if (threadIdx.x == 0) {
        float sc[NE];
        #pragma unroll
        for (int e = 0; e < NE; e++) sc[e] = s[e];

        float mx1 = -INFINITY; int i1 = 0;
        #pragma unroll
        for (int e = 0; e < NE; e++) if (sc[e] > mx1) { mx1 = sc[e]; i1 = e; }
        float sum1 = 0.f;
        #pragma unroll
        for (int e = 0; e < NE; e++) {
            float f = fmaxf(fabsf(sc[e]), mx1);
            bool masked = ((mx1 - sc[e]) / f) > 0.02f;
            if (!masked) sum1 += expf(sc[e] - mx1);
        }
        float g1 = 1.f / sum1;

        float mx2 = -INFINITY; int i2 = 0;
        #pragma unroll
        for (int e = 0; e < NE; e++) if (e != i1 && sc[e] > mx2) { mx2 = sc[e]; i2 = e; }
        float sum2 = 0.f;
        #pragma unroll
        for (int e = 0; e < NE; e++) {
            if (e == i1) continue;
            float f = fmaxf(fabsf(sc[e]), mx2);
            bool masked = ((mx2 - sc[e]) / f) > 0.02f;
            if (!masked) sum2 += expf(sc[e] - mx2);
        }
        float g2 = 1.f / sum2;

        int p1 = atomicAdd(&g_cnt[i1], 1);
        g_rows[i1 * NT + p1] = 2 * t;
        g_gw[2 * t] = g1;
        int p2 = atomicAdd(&g_cnt[i2], 1);
        g_rows[i2 * NT + p2] = 2 * t + 1;
        g_gw[2 * t + 1] = g2;
    }
}

// ---------------- grouped GEMM (tf32 wmma, cp.async double-buffered) ----------------
// A[M,K] row-major gathered, B[N,K] row-major (so B is used as col-major fragment)
// MODE 1: A = x (row = row_id>>1, K=NH), B = ws[e] [8192,2048], C = g_h rows (row_id)
// MODE 2: A = g_i (row = row_id,   K=NI), B = w2s[e] [2048,4096], C = atomicAdd into out scaled by g_gw
constexpr int BM = 128, BN = 128, BK = 32, KPAD = 36, CLD = BN + 4;
constexpr int STAGE_F = (BM + BN) * KPAD;          // 9216 floats = 36864 B
constexpr int PIPE_F  = 2 * STAGE_F;               // 18432 floats = 73728 B
constexpr int CS_F    = BM * CLD;                  // 16896 floats
constexpr int SMEM_BYTES = (PIPE_F > CS_F ? PIPE_F : CS_F) * 4; // 73728

template<int MODE>
__global__ void __launch_bounds__(256, 2) k_gemm(const float* __restrict__ Aarg,
                                                 const float* __restrict__ Barg,
                                                 float* __restrict__ Carg) {
    constexpr int K = (MODE == 1) ? NH : NI;
    constexpr int N = (MODE == 1) ? TWO_I : NH;

    int e = blockIdx.z;
    int cnt = g_cnt[e];
    int m0 = blockIdx.x * BM;
    if (m0 >= cnt) return;
    int n0 = blockIdx.y * BN;

    extern __shared__ float smem[];
    __shared__ int rowids[BM];

    int tid = threadIdx.x;
    if (tid < BM) rowids[tid] = (m0 + tid < cnt) ? g_rows[e * NT + m0 + tid] : -1;
    __syncthreads();

    const float* A = (MODE == 1) ? Aarg : (const float*)g_i;
    const float* Bexp = Barg + (size_t)e * N * K;

    // loader mapping: thread t loads row lr (0..127) of A and of B,
    // 4 float4 chunks at float offsets lc + 4j, lc = (t&1)*16
    int lr = tid >> 1;
    int lc = (tid & 1) * 16;
    int rid_l = rowids[lr];
    bool av = (rid_l >= 0);
    const float* aptr = A + (size_t)(av ? ((MODE == 1) ? (rid_l >> 1) : rid_l) : 0) * K + lc;
    const float* bptr = Bexp + (size_t)(n0 + lr) * K + lc;
    int aoff = lr * KPAD + lc;
    int boff = BM * KPAD + lr * KPAD + lc;

    int warp = tid >> 5;
    int wm = warp & 1;   // 64-row subtile
    int wn = warp >> 1;  // 32-col subtile

    wmma::fragment<wmma::accumulator, 16, 16, 8, float> acc[4][2];
    #pragma unroll
    for (int fm = 0; fm < 4; fm++)
        #pragma unroll
        for (int fn = 0; fn < 2; fn++)
            wmma::fill_fragment(acc[fm][fn], 0.f);

    // prologue: stage 0
    {
        float* st = smem;
        #pragma unroll
        for (int j = 0; j < 4; j++) {
            cpa16(st + aoff + j * 4, aptr + j * 4, av);
            cpa16(st + boff + j * 4, bptr + j * 4, true);
        }
        cp_commit();
    }

    int s = 0;
    for (int kb = 0; kb < K; kb += BK, s ^= 1) {
        bool more = (kb + BK < K);
        if (more) {
            float* st = smem + (s ^ 1) * STAGE_F;
            #pragma unroll
            for (int j = 0; j < 4; j++) {
                cpa16(st + aoff + j * 4, aptr + kb + BK + j * 4, av);
                cpa16(st + boff + j * 4, bptr + kb + BK + j * 4, true);
            }
            cp_commit();
            cp_wait<1>();
        } else {
            cp_wait<0>();
        }
        __syncthreads();

        // one-shot tf32 convert in place (each thread owns its loaded chunks)
        float* st = smem + s * STAGE_F;
        #pragma unroll
        for (int j = 0; j < 4; j++) {
            float4 va = *(float4*)(st + aoff + j * 4);
            va.x = wmma::__float_to_tf32(va.x);
            va.y = wmma::__float_to_tf32(va.y);
            va.z = wmma::__float_to_tf32(va.z);
            va.w = wmma::__float_to_tf32(va.w);
            *(float4*)(st + aoff + j * 4) = va;
            float4 vb = *(float4*)(st + boff + j * 4);
            vb.x = wmma::__float_to_tf32(vb.x);
            vb.y = wmma::__float_to_tf32(vb.y);
            vb.z = wmma::__float_to_tf32(vb.z);
            vb.w = wmma::__float_to_tf32(vb.w);
            *(float4*)(st + boff + j * 4) = vb;
        }
        __syncthreads();

        float* as = st;
        float* bs = st + BM * KPAD;
        #pragma unroll
        for (int kk = 0; kk < BK; kk += 8) {
            wmma::fragment<wmma::matrix_a, 16, 16, 8, wmma::precision::tf32, wmma::row_major> af[4];
            wmma::fragment<wmma::matrix_b, 16, 16, 8, wmma::precision::tf32, wmma::col_major> bf[2];
            #pragma unroll
            for (int fm = 0; fm < 4; fm++)
                wmma::load_matrix_sync(af[fm], as + (wm * 64 + fm * 16) * KPAD + kk, KPAD);
            #pragma unroll
            for (int fn = 0; fn < 2; fn++)
                wmma::load_matrix_sync(bf[fn], bs + (wn * 32 + fn * 16) * KPAD + kk, KPAD);
            #pragma unroll
            for (int fm = 0; fm < 4; fm++)
                #pragma unroll
                for (int fn = 0; fn < 2; fn++)
                    wmma::mma_sync(acc[fm][fn], af[fm], bf[fn], acc[fm][fn]);
        }
        __syncthreads();
    }

    // epilogue: stage tile to shared, then scattered row writes
    float* Cs = smem;
    #pragma unroll
    for (int fm = 0; fm < 4; fm++)
        #pragma unroll
        for (int fn = 0; fn < 2; fn++)
            wmma::store_matrix_sync(Cs + (size_t)(wm * 64 + fm * 16) * CLD + wn * 32 + fn * 16,
                                    acc[fm][fn], CLD, wmma::mem_row_major);
    __syncthreads();

    int r = tid >> 1;
    int ch = (tid & 1) * 64;
    int rid = rowids[r];
    if (rid >= 0) {
        const float* src = Cs + (size_t)r * CLD + ch;
        if (MODE == 1) {
            float* dst = g_h + (size_t)rid * TWO_I + n0 + ch;
            #pragma unroll
            for (int c = 0; c < 64; c += 4)
                *(float4*)(dst + c) = *(const float4*)(src + c);
        } else {
            float g = g_gw[rid];
            int tok = rid >> 1;
            float* dst = Carg + (size_t)tok * NH + n0 + ch;
            #pragma unroll
            for (int c = 0; c < 64; c++)
                atomicAdd(dst + c, g * src[c]);
        }
    }
}

// ---------------- silu(gate) * up ----------------
__global__ void k_silu() {
    size_t idx = (size_t)blockIdx.x * blockDim.x + threadIdx.x;
    size_t total = (size_t)NSLOT * NI / 4;
    if (idx >= total) return;
    size_t r = idx / (NI / 4);
    size_t c = (idx % (NI / 4)) * 4;
    float4 gv = *(const float4*)(g_h + r * TWO_I + c);
    float4 uv = *(const float4*)(g_h + r * TWO_I + NI + c);
    float4 o;
    o.x = gv.x / (1.f + expf(-gv.x)) * uv.x;
    o.y = gv.y / (1.f + expf(-gv.y)) * uv.y;
    o.z = gv.z / (1.f + expf(-gv.z)) * uv.z;
    o.w = gv.w / (1.f + expf(-gv.w)) * uv.w;
    *(float4*)(g_i + r * NI + c) = o;
}

// ---------------- launch ----------------
extern "C" void kernel_launch(void* const* d_in, const int* in_sizes, int n_in,
                              void* d_out, int out_size) {
    const float* x     = (const float*)d_in[0];
    const float* gatew = (const float*)d_in[1];
    const float* ws    = (const float*)d_in[2];
    const float* w2s   = (const float*)d_in[3];
    float* out = (float*)d_out;

    cudaFuncSetAttribute((const void*)k_gemm<1>, cudaFuncAttributeMaxDynamicSharedMemorySize, SMEM_BYTES);
    cudaFuncSetAttribute((const void*)k_gemm<2>, cudaFuncAttributeMaxDynamicSharedMemorySize, SMEM_BYTES);

    cudaMemsetAsync(d_out, 0, (size_t)out_size * sizeof(float), 0);
    k_zero_cnt<<<1, 32>>>();
    k_router<<<NT, 256>>>(x, gatew);

    dim3 g1(NT / BM, TWO_I / BN, NE);
    k_gemm<1><<<g1, 256, SMEM_BYTES>>>(x, ws, nullptr);

    k_silu<<<(int)(((size_t)NSLOT * NI / 4 + 255) / 256), 256>>>();

    dim3 g2(NT / BM, NH / BN, NE);
    k_gemm<2><<<g2, 256, SMEM_BYTES>>>(nullptr, w2s, out);
}